// round 16
// baseline (speedup 1.0000x reference)
#include <cuda_runtime.h>
#include <cuda_fp16.h>

#define NN 200000
#define NE 400000
#define NG 64
#define HD 128
#define IND 5
#define L0W 16          // layer-0 padded row width (halves)
#define TROWS 64
#define SROW 136        // f16 tile row stride (halves): ldmatrix conflict-free
#define SPST 12         // partial-sum row stride (floats): 48B, 16B-aligned
#define GRID_P 304      // persistent CTAs (2 per SM, 152 SMs)

// ---------------- device scratch (allocation-free rule) ----------------
__device__ __half g_h5h[(size_t)NN * L0W];  // layer-0 padded fp16 (x + aggr)
__device__ __half g_h[(size_t)NN * HD];     // accumulation base (y + aggr), fp16
__device__ __half g_bufA[(size_t)NN * HD];  // layer outputs ping (fp16)
__device__ __half g_bufB[(size_t)NN * HD];  // layer outputs pong (fp16)
__device__ float  g_pool[NG * HD];
__device__ int    g_cnt[NG];

// ---------------- helpers ----------------
__device__ __forceinline__ unsigned packh2(float a, float b) {
    half2 h = __floats2half2_rn(a, b);
    return *(unsigned*)&h;
}
__device__ __forceinline__ void ldmA(unsigned a[4], unsigned saddr) {
    asm volatile("ldmatrix.sync.aligned.m8n8.x4.shared.b16 {%0,%1,%2,%3}, [%4];"
                 : "=r"(a[0]), "=r"(a[1]), "=r"(a[2]), "=r"(a[3]) : "r"(saddr));
}
__device__ __forceinline__ void mma16(float* d, const unsigned* a, unsigned b0, unsigned b1) {
    asm volatile("mma.sync.aligned.m16n8k16.row.col.f32.f16.f16.f32 "
                 "{%0,%1,%2,%3}, {%4,%5,%6,%7}, {%8,%9}, {%0,%1,%2,%3};"
                 : "+f"(d[0]), "+f"(d[1]), "+f"(d[2]), "+f"(d[3])
                 : "r"(a[0]), "r"(a[1]), "r"(a[2]), "r"(a[3]), "r"(b0), "r"(b1));
}
__device__ __forceinline__ void cp_async16(unsigned saddr, const void* gptr) {
    asm volatile("cp.async.cg.shared.global [%0], [%1], 16;" :: "r"(saddr), "l"(gptr));
}
#define CP_COMMIT() asm volatile("cp.async.commit_group;" ::: "memory")
#define CP_WAIT0()  asm volatile("cp.async.wait_group 0;" ::: "memory")

// ---------------- layer-0 prep (+ pool zeroing fused: disjoint buffers) ----------------
__global__ void copy5h(const float* __restrict__ x) {
    int n = blockIdx.x * blockDim.x + threadIdx.x;
    if (n < NG * HD) g_pool[n] = 0.f;          // independent of h5h writes
    if (n < NG) g_cnt[n] = 0;
    if (n >= NN) return;
    __half v[16];
#pragma unroll
    for (int j = 0; j < L0W; j++)
        v[j] = __float2half_rn(j < IND ? __ldg(x + n * IND + j) : 0.f);
    *(uint4*)(g_h5h + (size_t)n * L0W)     = *(uint4*)v;
    *(uint4*)(g_h5h + (size_t)n * L0W + 8) = *(uint4*)(v + 8);
}

__global__ void edge5h(const int* __restrict__ src, const int* __restrict__ dst,
                       const float* __restrict__ ea,
                       const float* __restrict__ ew, const float* __restrict__ eb,
                       const float* __restrict__ x) {
    int e = blockIdx.x * blockDim.x + threadIdx.x;
    if (e >= NE) return;
    int s = __ldg(src + e), d = __ldg(dst + e);
    float a = __ldg(ea + e);
    float m[IND];
#pragma unroll
    for (int j = 0; j < IND; j++)
        m[j] = fmaxf(__ldg(x + s * IND + j) + fmaf(a, __ldg(ew + j), __ldg(eb + j)), 0.f);
    unsigned p0 = packh2(m[0], m[1]);
    unsigned p1 = packh2(m[2], m[3]);
    __half h4 = __float2half_rn(m[4]);
    __half* pd = g_h5h + (size_t)d * L0W;
    asm volatile("red.global.add.noftz.v2.f16x2 [%0], {%1, %2};"
                 :: "l"(pd), "r"(p0), "r"(p1) : "memory");
    asm volatile("red.global.add.noftz.f16 [%0], %1;"
                 :: "l"(pd + 4), "h"(*(unsigned short*)&h4) : "memory");
}

// fp16 edge message + scatter (HD layers). Persistent; unroll 2 (validated);
// streaming hints on the read-once index/attr arrays to protect L2 for gathers.
__global__ void __launch_bounds__(256, 6) edge128h(
        const int* __restrict__ src, const int* __restrict__ dst,
        const float* __restrict__ ea,
        const float* __restrict__ ew, const float* __restrict__ eb,
        const __half* __restrict__ x, __half* __restrict__ h) {
    const int lane = threadIdx.x & 15;        // halves [lane*8, lane*8+8)
    const int g0 = (blockIdx.x * blockDim.x + threadIdx.x) >> 4;
    const int gs = (gridDim.x * blockDim.x) >> 4;
    const float4 w0 = __ldg((const float4*)ew + lane * 2);
    const float4 w1 = __ldg((const float4*)ew + lane * 2 + 1);
    const float4 c0 = __ldg((const float4*)eb + lane * 2);
    const float4 c1 = __ldg((const float4*)eb + lane * 2 + 1);
#pragma unroll 2
    for (int e = g0; e < NE; e += gs) {
        int s = __ldcs(src + e), d = __ldcs(dst + e);
        float a = __ldcs(ea + e);
        uint4 xv = __ldg((const uint4*)(x + (size_t)s * HD) + lane);
        float2 x0 = __half22float2(*(half2*)&xv.x);
        float2 x1 = __half22float2(*(half2*)&xv.y);
        float2 x2 = __half22float2(*(half2*)&xv.z);
        float2 x3 = __half22float2(*(half2*)&xv.w);
        unsigned m0 = packh2(fmaxf(x0.x + fmaf(a, w0.x, c0.x), 0.f),
                             fmaxf(x0.y + fmaf(a, w0.y, c0.y), 0.f));
        unsigned m1 = packh2(fmaxf(x1.x + fmaf(a, w0.z, c0.z), 0.f),
                             fmaxf(x1.y + fmaf(a, w0.w, c0.w), 0.f));
        unsigned m2 = packh2(fmaxf(x2.x + fmaf(a, w1.x, c1.x), 0.f),
                             fmaxf(x2.y + fmaf(a, w1.y, c1.y), 0.f));
        unsigned m3 = packh2(fmaxf(x3.x + fmaf(a, w1.z, c1.z), 0.f),
                             fmaxf(x3.y + fmaf(a, w1.w, c1.w), 0.f));
        __half* p = h + (size_t)d * HD + lane * 8;
        asm volatile("red.global.add.noftz.v4.f16x2 [%0], {%1, %2, %3, %4};"
                     :: "l"(p), "r"(m0), "r"(m1), "r"(m2), "r"(m3) : "memory");
    }
}

// ---------------- fused MLP + LN (+ fused pooling), fp16 m16n8k16 ----------------
// smem (bytes): [0,3072) params | sA0 | sA1 | sMid | sp | batch ids
#define TILEB   (TROWS * SROW * 2)         // 17408
#define OFF_A0  3072
#define OFF_A1  (OFF_A0 + TILEB)
#define OFF_MID (OFF_A1 + TILEB)
#define OFF_SP  (OFF_MID + TILEB)
#define OFF_BT  (OFF_SP + 2 * TROWS * SPST * 4)
#define SMEM_TOT (OFF_BT + TROWS * 4)
#define NTILE (NN / TROWS)

template <int DIN, bool DUAL, bool POOL>
__global__ void __launch_bounds__(256, 2) mlp_tc(
        const __half* __restrict__ hin,
        const float* __restrict__ w1, const float* __restrict__ b1,
        const float* __restrict__ w2, const float* __restrict__ b2,
        const float* __restrict__ gam, const float* __restrict__ bet,
        __half* __restrict__ out, __half* __restrict__ hdup,
        const int* __restrict__ batch) {
    extern __shared__ char smem[];
    float* s_b1 = (float*)smem;
    float* s_b2 = s_b1 + 128;
    float* s_g  = s_b1 + 256;
    float* s_bt = s_b1 + 384;
    half*  sA0  = (half*)(smem + OFF_A0);
    half*  sA1  = (half*)(smem + OFF_A1);
    half*  sMid = (half*)(smem + OFF_MID);
    float* sp_s = (float*)(smem + OFF_SP);
    float* sp_q = sp_s + TROWS * SPST;
    int*   sbat = (int*)(smem + OFF_BT);

    const int tid = threadIdx.x;
    const int w = tid >> 5, lane = tid & 31;
    const int qr = lane >> 2, qc = lane & 3;
    const int wbase = w * 16;
    const int lm_r = ((lane >> 3) & 1) * 8 + (lane & 7);
    const int lm_c = (lane >> 4) * 8;
    constexpr int NCP = (DIN == HD) ? 16 : 2;   // A-row width in 8-half groups

    if (tid < 128) {
        s_b1[tid] = __ldg(b1 + tid);
        s_b2[tid] = __ldg(b2 + tid);
        s_g[tid]  = __ldg(gam + tid);
        s_bt[tid] = __ldg(bet + tid);
    }

    // ---- W fragments: loaded ONCE per persistent CTA ----
    constexpr int NKS1 = (DIN == HD) ? 8 : 1;
    unsigned wf1[2][NKS1][2], wf2[2][8][2];
#pragma unroll
    for (int nt = 0; nt < 2; nt++) {
        int n = wbase + nt * 8 + qr;
#pragma unroll
        for (int kk = 0; kk < NKS1; kk++) {
            int k0 = kk * 16 + 2 * qc;
            float f0 = (k0 < DIN)     ? __ldg(w1 + (size_t)k0 * HD + n)       : 0.f;
            float f1 = (k0 + 1 < DIN) ? __ldg(w1 + (size_t)(k0 + 1) * HD + n) : 0.f;
            float f2 = (k0 + 8 < DIN) ? __ldg(w1 + (size_t)(k0 + 8) * HD + n) : 0.f;
            float f3 = (k0 + 9 < DIN) ? __ldg(w1 + (size_t)(k0 + 9) * HD + n) : 0.f;
            wf1[nt][kk][0] = packh2(f0, f1);
            wf1[nt][kk][1] = packh2(f2, f3);
        }
#pragma unroll
        for (int kk = 0; kk < 8; kk++) {
            int k0 = kk * 16 + 2 * qc;
            wf2[nt][kk][0] = packh2(__ldg(w2 + (size_t)k0 * HD + n),
                                    __ldg(w2 + (size_t)(k0 + 1) * HD + n));
            wf2[nt][kk][1] = packh2(__ldg(w2 + (size_t)(k0 + 8) * HD + n),
                                    __ldg(w2 + (size_t)(k0 + 9) * HD + n));
        }
    }
    __syncthreads();

    const unsigned sMid_base = (unsigned)__cvta_generic_to_shared(sMid);
    const unsigned sA0_base  = (unsigned)__cvta_generic_to_shared(sA0);
    const unsigned sA1_base  = (unsigned)__cvta_generic_to_shared(sA1);

    // prime: prefetch first tile into sA0
    int pb = 0;
    {
        int n0 = blockIdx.x * TROWS;
        for (int idx = tid; idx < TROWS * NCP; idx += 256) {
            int row = idx / NCP, q = idx % NCP;
            cp_async16(sA0_base + (row * SROW + q * 8) * 2,
                       hin + (size_t)(n0 + row) * (NCP * 8) + q * 8);
        }
        CP_COMMIT();
    }

    for (int tile = blockIdx.x; tile < NTILE; tile += GRID_P) {
        const int n0 = tile * TROWS;
        half* sAc = pb ? sA1 : sA0;
        const unsigned sAc_base = pb ? sA1_base : sA0_base;

        CP_WAIT0();
        __syncthreads();                 // A_t visible; prev-tile smem reuse done
        int tn = tile + GRID_P;
        if (tn < NTILE) {                // prefetch next tile into alternate buf
            const unsigned sAn_base = pb ? sA0_base : sA1_base;
            int m0 = tn * TROWS;
            for (int idx = tid; idx < TROWS * NCP; idx += 256) {
                int row = idx / NCP, q = idx % NCP;
                cp_async16(sAn_base + (row * SROW + q * 8) * 2,
                           hin + (size_t)(m0 + row) * (NCP * 8) + q * 8);
            }
        }
        CP_COMMIT();
        if (POOL && tid < TROWS) sbat[tid] = __ldg(batch + n0 + tid);

        // ---- GEMM1 + bias1 + ReLU -> sMid ----
#pragma unroll 1
        for (int mt = 0; mt < TROWS / 16; mt++) {
            float d0[4] = {0, 0, 0, 0}, d1[4] = {0, 0, 0, 0};
            int r0 = mt * 16;
#pragma unroll
            for (int kk = 0; kk < NKS1; kk++) {
                unsigned a[4];
                ldmA(a, sAc_base + ((r0 + lm_r) * SROW + kk * 16 + lm_c) * 2);
                mma16(d0, a, wf1[0][kk][0], wf1[0][kk][1]);
                mma16(d1, a, wf1[1][kk][0], wf1[1][kk][1]);
            }
#pragma unroll
            for (int nt = 0; nt < 2; nt++) {
                float* d = nt ? d1 : d0;
                int c0 = wbase + nt * 8 + 2 * qc;
                *(unsigned*)(sMid + (r0 + qr) * SROW + c0) =
                    packh2(fmaxf(d[0] + s_b1[c0], 0.f), fmaxf(d[1] + s_b1[c0 + 1], 0.f));
                *(unsigned*)(sMid + (r0 + 8 + qr) * SROW + c0) =
                    packh2(fmaxf(d[2] + s_b1[c0], 0.f), fmaxf(d[3] + s_b1[c0 + 1], 0.f));
            }
        }
        __syncthreads();

        // ---- GEMM2 + bias2: partial LN sums -> sp, fp16 values -> sAc ----
#pragma unroll 1
        for (int mt = 0; mt < TROWS / 16; mt++) {
            float d0[4] = {0, 0, 0, 0}, d1[4] = {0, 0, 0, 0};
            int r0 = mt * 16;
#pragma unroll
            for (int kk = 0; kk < 8; kk++) {
                unsigned a[4];
                ldmA(a, sMid_base + ((r0 + lm_r) * SROW + kk * 16 + lm_c) * 2);
                mma16(d0, a, wf2[0][kk][0], wf2[0][kk][1]);
                mma16(d1, a, wf2[1][kk][0], wf2[1][kk][1]);
            }
            {
                int c0 = wbase + 2 * qc, c1 = wbase + 8 + 2 * qc;
                d0[0] += s_b2[c0]; d0[1] += s_b2[c0 + 1];
                d0[2] += s_b2[c0]; d0[3] += s_b2[c0 + 1];
                d1[0] += s_b2[c1]; d1[1] += s_b2[c1 + 1];
                d1[2] += s_b2[c1]; d1[3] += s_b2[c1 + 1];
            }
            float sa = d0[0] + d0[1] + d1[0] + d1[1];
            float sb = d0[2] + d0[3] + d1[2] + d1[3];
            float qa = d0[0] * d0[0] + d0[1] * d0[1] + d1[0] * d1[0] + d1[1] * d1[1];
            float qb = d0[2] * d0[2] + d0[3] * d0[3] + d1[2] * d1[2] + d1[3] * d1[3];
#pragma unroll
            for (int o = 1; o <= 2; o <<= 1) {
                sa += __shfl_xor_sync(0xffffffffu, sa, o);
                sb += __shfl_xor_sync(0xffffffffu, sb, o);
                qa += __shfl_xor_sync(0xffffffffu, qa, o);
                qb += __shfl_xor_sync(0xffffffffu, qb, o);
            }
            if (qc == 0) {
                sp_s[(r0 + qr) * SPST + w] = sa;
                sp_s[(r0 + 8 + qr) * SPST + w] = sb;
                sp_q[(r0 + qr) * SPST + w] = qa;
                sp_q[(r0 + 8 + qr) * SPST + w] = qb;
            }
            {
                int c0 = wbase + 2 * qc;
                *(unsigned*)(sAc + (r0 + qr) * SROW + c0)      = packh2(d0[0], d0[1]);
                *(unsigned*)(sAc + (r0 + qr) * SROW + c0 + 8)  = packh2(d1[0], d1[1]);
                *(unsigned*)(sAc + (r0 + 8 + qr) * SROW + c0)     = packh2(d0[2], d0[3]);
                *(unsigned*)(sAc + (r0 + 8 + qr) * SROW + c0 + 8) = packh2(d1[2], d1[3]);
            }
        }
        __syncthreads();

        // ---- LN apply + ReLU + store (gmem for layers 0/1; smem stash for pool) ----
        for (int idx = tid; idx < TROWS * 16; idx += 256) {
            int row = idx >> 4, q = idx & 15;
            float4 sa = *(const float4*)(sp_s + row * SPST);
            float4 sb = *(const float4*)(sp_s + row * SPST + 4);
            float4 qa = *(const float4*)(sp_q + row * SPST);
            float4 qb = *(const float4*)(sp_q + row * SPST + 4);
            float s  = sa.x + sa.y + sa.z + sa.w + sb.x + sb.y + sb.z + sb.w;
            float s2 = qa.x + qa.y + qa.z + qa.w + qb.x + qb.y + qb.z + qb.w;
            float mean = s * (1.f / HD);
            float var = s2 * (1.f / HD) - mean * mean;
            float rstd = rsqrtf(var + 1e-5f);
            uint4 v = *(const uint4*)(sAc + row * SROW + q * 8);
            float2 v0 = __half22float2(*(half2*)&v.x);
            float2 v1 = __half22float2(*(half2*)&v.y);
            float2 v2 = __half22float2(*(half2*)&v.z);
            float2 v3 = __half22float2(*(half2*)&v.w);
            int c = q * 8;
            uint4 o;
            o.x = packh2(fmaxf((v0.x - mean) * rstd * s_g[c + 0] + s_bt[c + 0], 0.f),
                         fmaxf((v0.y - mean) * rstd * s_g[c + 1] + s_bt[c + 1], 0.f));
            o.y = packh2(fmaxf((v1.x - mean) * rstd * s_g[c + 2] + s_bt[c + 2], 0.f),
                         fmaxf((v1.y - mean) * rstd * s_g[c + 3] + s_bt[c + 3], 0.f));
            o.z = packh2(fmaxf((v2.x - mean) * rstd * s_g[c + 4] + s_bt[c + 4], 0.f),
                         fmaxf((v2.y - mean) * rstd * s_g[c + 5] + s_bt[c + 5], 0.f));
            o.w = packh2(fmaxf((v3.x - mean) * rstd * s_g[c + 6] + s_bt[c + 6], 0.f),
                         fmaxf((v3.y - mean) * rstd * s_g[c + 7] + s_bt[c + 7], 0.f));
            if (POOL) {
                *(uint4*)(sMid + row * SROW + c) = o;    // pooling consumes smem only
            } else {
                size_t off = (size_t)(n0 + row) * HD + c;
                *(uint4*)(out + off) = o;
                if (DUAL) *(uint4*)(hdup + off) = o;
            }
        }

        // ---- fused pooling: segmented reduction, 2 threads per column ----
        if (POOL) {
            __syncthreads();             // sMid stashes + sbat visible
            int j = tid & 127;
            int rbeg = (tid >> 7) * (TROWS / 2);       // 0 or 32
            int rend = rbeg + TROWS / 2;
            float acc = 0.f;
            int cnt = 0, cur = sbat[rbeg];
            for (int r = rbeg; r < rend; r++) {
                int gp = sbat[r];
                if (gp != cur) {
                    atomicAdd(&g_pool[cur * HD + j], acc);
                    if (j == 0) atomicAdd(&g_cnt[cur], cnt);
                    acc = 0.f; cnt = 0; cur = gp;
                }
                acc += __half2float(sMid[r * SROW + j]);
                cnt++;
            }
            atomicAdd(&g_pool[cur * HD + j], acc);
            if (j == 0) atomicAdd(&g_cnt[cur], cnt);
        }
        pb ^= 1;
    }
}

// ---------------- pooling epilogue ----------------
__global__ void finalize(float* __restrict__ out) {
    int g = blockIdx.x, j = threadIdx.x;
    float s = g_pool[g * HD + j];
    int c = g_cnt[g];
    float cf = (float)(c > 1 ? c : 1);
    out[g * 2 * HD + j]      = s / cf;
    out[g * 2 * HD + HD + j] = s;
}

// ---------------------------------------------------------------------------
extern "C" void kernel_launch(void* const* d_in, const int* in_sizes, int n_in,
                              void* d_out, int out_size) {
    const float* x     = (const float*)d_in[0];
    const int*   ei    = (const int*)d_in[1];
    const float* ea    = (const float*)d_in[2];
    const int*   batch = (const int*)d_in[3];
    const float* P[24];
    for (int i = 0; i < 24; i++) P[i] = (const float*)d_in[4 + i];
    const int* esrc = ei;
    const int* edst = ei + NE;

    __half *h5h, *h, *bufA, *bufB;
    cudaGetSymbolAddress((void**)&h5h, g_h5h);
    cudaGetSymbolAddress((void**)&h, g_h);
    cudaGetSymbolAddress((void**)&bufA, g_bufA);
    cudaGetSymbolAddress((void**)&bufB, g_bufB);

    cudaFuncSetAttribute(mlp_tc<IND, true, false>, cudaFuncAttributeMaxDynamicSharedMemorySize, SMEM_TOT);
    cudaFuncSetAttribute(mlp_tc<HD, true, false>,  cudaFuncAttributeMaxDynamicSharedMemorySize, SMEM_TOT);
    cudaFuncSetAttribute(mlp_tc<HD, false, true>,  cudaFuncAttributeMaxDynamicSharedMemorySize, SMEM_TOT);

    const int TB = 256;
    const int GEDGE = 3125;   // 3125*256/16 = 50000 edge slots, 8 iters

    // ---- layer 0 (din = 5, padded fp16; pool zeroing fused) ----
    copy5h<<<(NN + TB - 1) / TB, TB>>>(x);
    edge5h<<<(NE + TB - 1) / TB, TB>>>(esrc, edst, ea, P[0], P[1], x);
    mlp_tc<IND, true, false><<<GRID_P, 256, SMEM_TOT>>>(h5h, P[2], P[3], P[4], P[5], P[6], P[7], bufA, h, nullptr);

    // ---- layer 1 ----
    edge128h<<<GEDGE, TB>>>(esrc, edst, ea, P[8], P[9], bufA, h);
    mlp_tc<HD, true, false><<<GRID_P, 256, SMEM_TOT>>>(h, P[10], P[11], P[12], P[13], P[14], P[15], bufB, h, nullptr);

    // ---- layer 2 (pooling fused; no gmem output store) ----
    edge128h<<<GEDGE, TB>>>(esrc, edst, ea, P[16], P[17], bufB, h);
    mlp_tc<HD, false, true><<<GRID_P, 256, SMEM_TOT>>>(h, P[18], P[19], P[20], P[21], P[22], P[23], nullptr, nullptr, batch);

    // ---- finalize ----
    finalize<<<NG, HD>>>((float*)d_out);
}

// round 17
// speedup vs baseline: 1.0320x; 1.0320x over previous
#include <cuda_runtime.h>
#include <cuda_fp16.h>

#define NN 200000
#define NE 400000
#define NG 64
#define HD 128
#define IND 5
#define L0W 16          // layer-0 padded row width (halves)
#define TROWS 64
#define SROW 136        // f16 tile row stride (halves): ldmatrix conflict-free
#define SPST 12         // partial-sum row stride (floats): 48B, 16B-aligned
#define GRID_P 304      // persistent CTAs (2 per SM, 152 SMs)

// ---------------- device scratch (allocation-free rule) ----------------
__device__ __half g_h5h[(size_t)NN * L0W];  // layer-0 padded fp16 (x + aggr)
__device__ __half g_h[(size_t)NN * HD];     // accumulation base (y + aggr), fp16
__device__ __half g_bufA[(size_t)NN * HD];  // layer outputs ping (fp16)
__device__ __half g_bufB[(size_t)NN * HD];  // layer outputs pong (fp16)
__device__ float  g_pool[NG * HD];
__device__ int    g_cnt[NG];

// ---------------- helpers ----------------
__device__ __forceinline__ unsigned packh2(float a, float b) {
    half2 h = __floats2half2_rn(a, b);
    return *(unsigned*)&h;
}
__device__ __forceinline__ void ldmA(unsigned a[4], unsigned saddr) {
    asm volatile("ldmatrix.sync.aligned.m8n8.x4.shared.b16 {%0,%1,%2,%3}, [%4];"
                 : "=r"(a[0]), "=r"(a[1]), "=r"(a[2]), "=r"(a[3]) : "r"(saddr));
}
__device__ __forceinline__ void mma16(float* d, const unsigned* a, unsigned b0, unsigned b1) {
    asm volatile("mma.sync.aligned.m16n8k16.row.col.f32.f16.f16.f32 "
                 "{%0,%1,%2,%3}, {%4,%5,%6,%7}, {%8,%9}, {%0,%1,%2,%3};"
                 : "+f"(d[0]), "+f"(d[1]), "+f"(d[2]), "+f"(d[3])
                 : "r"(a[0]), "r"(a[1]), "r"(a[2]), "r"(a[3]), "r"(b0), "r"(b1));
}
__device__ __forceinline__ void cp_async16(unsigned saddr, const void* gptr) {
    asm volatile("cp.async.cg.shared.global [%0], [%1], 16;" :: "r"(saddr), "l"(gptr));
}
#define CP_COMMIT() asm volatile("cp.async.commit_group;" ::: "memory")
#define CP_WAIT0()  asm volatile("cp.async.wait_group 0;" ::: "memory")

// ---------------- layer-0 prep (+ pool zeroing fused: disjoint buffers) ----------------
__global__ void copy5h(const float* __restrict__ x) {
    int n = blockIdx.x * blockDim.x + threadIdx.x;
    if (n < NG * HD) g_pool[n] = 0.f;          // independent of h5h writes
    if (n < NG) g_cnt[n] = 0;
    if (n >= NN) return;
    __half v[16];
#pragma unroll
    for (int j = 0; j < L0W; j++)
        v[j] = __float2half_rn(j < IND ? __ldg(x + n * IND + j) : 0.f);
    *(uint4*)(g_h5h + (size_t)n * L0W)     = *(uint4*)v;
    *(uint4*)(g_h5h + (size_t)n * L0W + 8) = *(uint4*)(v + 8);
}

__global__ void edge5h(const int* __restrict__ src, const int* __restrict__ dst,
                       const float* __restrict__ ea,
                       const float* __restrict__ ew, const float* __restrict__ eb,
                       const float* __restrict__ x) {
    int e = blockIdx.x * blockDim.x + threadIdx.x;
    if (e >= NE) return;
    int s = __ldg(src + e), d = __ldg(dst + e);
    float a = __ldg(ea + e);
    float m[IND];
#pragma unroll
    for (int j = 0; j < IND; j++)
        m[j] = fmaxf(__ldg(x + s * IND + j) + fmaf(a, __ldg(ew + j), __ldg(eb + j)), 0.f);
    unsigned p0 = packh2(m[0], m[1]);
    unsigned p1 = packh2(m[2], m[3]);
    __half h4 = __float2half_rn(m[4]);
    __half* pd = g_h5h + (size_t)d * L0W;
    asm volatile("red.global.add.noftz.v2.f16x2 [%0], {%1, %2};"
                 :: "l"(pd), "r"(p0), "r"(p1) : "memory");
    asm volatile("red.global.add.noftz.f16 [%0], %1;"
                 :: "l"(pd + 4), "h"(*(unsigned short*)&h4) : "memory");
}

// fp16 edge message + scatter (HD layers). Persistent; unroll 2; __ldg (validated).
__global__ void __launch_bounds__(256, 6) edge128h(
        const int* __restrict__ src, const int* __restrict__ dst,
        const float* __restrict__ ea,
        const float* __restrict__ ew, const float* __restrict__ eb,
        const __half* __restrict__ x, __half* __restrict__ h) {
    const int lane = threadIdx.x & 15;        // halves [lane*8, lane*8+8)
    const int g0 = (blockIdx.x * blockDim.x + threadIdx.x) >> 4;
    const int gs = (gridDim.x * blockDim.x) >> 4;
    const float4 w0 = __ldg((const float4*)ew + lane * 2);
    const float4 w1 = __ldg((const float4*)ew + lane * 2 + 1);
    const float4 c0 = __ldg((const float4*)eb + lane * 2);
    const float4 c1 = __ldg((const float4*)eb + lane * 2 + 1);
#pragma unroll 2
    for (int e = g0; e < NE; e += gs) {
        int s = __ldg(src + e), d = __ldg(dst + e);
        float a = __ldg(ea + e);
        uint4 xv = __ldg((const uint4*)(x + (size_t)s * HD) + lane);
        float2 x0 = __half22float2(*(half2*)&xv.x);
        float2 x1 = __half22float2(*(half2*)&xv.y);
        float2 x2 = __half22float2(*(half2*)&xv.z);
        float2 x3 = __half22float2(*(half2*)&xv.w);
        unsigned m0 = packh2(fmaxf(x0.x + fmaf(a, w0.x, c0.x), 0.f),
                             fmaxf(x0.y + fmaf(a, w0.y, c0.y), 0.f));
        unsigned m1 = packh2(fmaxf(x1.x + fmaf(a, w0.z, c0.z), 0.f),
                             fmaxf(x1.y + fmaf(a, w0.w, c0.w), 0.f));
        unsigned m2 = packh2(fmaxf(x2.x + fmaf(a, w1.x, c1.x), 0.f),
                             fmaxf(x2.y + fmaf(a, w1.y, c1.y), 0.f));
        unsigned m3 = packh2(fmaxf(x3.x + fmaf(a, w1.z, c1.z), 0.f),
                             fmaxf(x3.y + fmaf(a, w1.w, c1.w), 0.f));
        __half* p = h + (size_t)d * HD + lane * 8;
        asm volatile("red.global.add.noftz.v4.f16x2 [%0], {%1, %2, %3, %4};"
                     :: "l"(p), "r"(m0), "r"(m1), "r"(m2), "r"(m3) : "memory");
    }
}

// ---------------- fused MLP + LN (+ fused pooling), fp16 m16n8k16 ----------------
// smem (bytes): [0,3072) params | sA0 | sA1 | sMid | sp | batch ids
#define TILEB   (TROWS * SROW * 2)         // 17408
#define OFF_A0  3072
#define OFF_A1  (OFF_A0 + TILEB)
#define OFF_MID (OFF_A1 + TILEB)
#define OFF_SP  (OFF_MID + TILEB)
#define OFF_BT  (OFF_SP + 2 * TROWS * SPST * 4)
#define SMEM_TOT (OFF_BT + TROWS * 4)
#define NTILE (NN / TROWS)

template <int DIN, bool DUAL, bool POOL>
__global__ void __launch_bounds__(256, 2) mlp_tc(
        const __half* __restrict__ hin,
        const float* __restrict__ w1, const float* __restrict__ b1,
        const float* __restrict__ w2, const float* __restrict__ b2,
        const float* __restrict__ gam, const float* __restrict__ bet,
        __half* __restrict__ out, __half* __restrict__ hdup,
        const int* __restrict__ batch) {
    extern __shared__ char smem[];
    float* s_b1 = (float*)smem;
    float* s_b2 = s_b1 + 128;
    float* s_g  = s_b1 + 256;
    float* s_bt = s_b1 + 384;
    half*  sA0  = (half*)(smem + OFF_A0);
    half*  sA1  = (half*)(smem + OFF_A1);
    half*  sMid = (half*)(smem + OFF_MID);
    float* sp_s = (float*)(smem + OFF_SP);
    float* sp_q = sp_s + TROWS * SPST;
    int*   sbat = (int*)(smem + OFF_BT);

    const int tid = threadIdx.x;
    const int w = tid >> 5, lane = tid & 31;
    const int qr = lane >> 2, qc = lane & 3;
    const int wbase = w * 16;
    const int lm_r = ((lane >> 3) & 1) * 8 + (lane & 7);
    const int lm_c = (lane >> 4) * 8;
    constexpr int NCP = (DIN == HD) ? 16 : 2;   // A-row width in 8-half groups

    if (tid < 128) {
        s_b1[tid] = __ldg(b1 + tid);
        s_b2[tid] = __ldg(b2 + tid);
        s_g[tid]  = __ldg(gam + tid);
        s_bt[tid] = __ldg(bet + tid);
    }

    // ---- W fragments: loaded ONCE per persistent CTA ----
    constexpr int NKS1 = (DIN == HD) ? 8 : 1;
    unsigned wf1[2][NKS1][2], wf2[2][8][2];
#pragma unroll
    for (int nt = 0; nt < 2; nt++) {
        int n = wbase + nt * 8 + qr;
#pragma unroll
        for (int kk = 0; kk < NKS1; kk++) {
            int k0 = kk * 16 + 2 * qc;
            float f0 = (k0 < DIN)     ? __ldg(w1 + (size_t)k0 * HD + n)       : 0.f;
            float f1 = (k0 + 1 < DIN) ? __ldg(w1 + (size_t)(k0 + 1) * HD + n) : 0.f;
            float f2 = (k0 + 8 < DIN) ? __ldg(w1 + (size_t)(k0 + 8) * HD + n) : 0.f;
            float f3 = (k0 + 9 < DIN) ? __ldg(w1 + (size_t)(k0 + 9) * HD + n) : 0.f;
            wf1[nt][kk][0] = packh2(f0, f1);
            wf1[nt][kk][1] = packh2(f2, f3);
        }
#pragma unroll
        for (int kk = 0; kk < 8; kk++) {
            int k0 = kk * 16 + 2 * qc;
            wf2[nt][kk][0] = packh2(__ldg(w2 + (size_t)k0 * HD + n),
                                    __ldg(w2 + (size_t)(k0 + 1) * HD + n));
            wf2[nt][kk][1] = packh2(__ldg(w2 + (size_t)(k0 + 8) * HD + n),
                                    __ldg(w2 + (size_t)(k0 + 9) * HD + n));
        }
    }
    __syncthreads();

    const unsigned sMid_base = (unsigned)__cvta_generic_to_shared(sMid);
    const unsigned sA0_base  = (unsigned)__cvta_generic_to_shared(sA0);
    const unsigned sA1_base  = (unsigned)__cvta_generic_to_shared(sA1);

    // prime: prefetch first tile into sA0
    int pb = 0;
    {
        int n0 = blockIdx.x * TROWS;
        for (int idx = tid; idx < TROWS * NCP; idx += 256) {
            int row = idx / NCP, q = idx % NCP;
            cp_async16(sA0_base + (row * SROW + q * 8) * 2,
                       hin + (size_t)(n0 + row) * (NCP * 8) + q * 8);
        }
        CP_COMMIT();
    }

    for (int tile = blockIdx.x; tile < NTILE; tile += GRID_P) {
        const int n0 = tile * TROWS;
        half* sAc = pb ? sA1 : sA0;
        const unsigned sAc_base = pb ? sA1_base : sA0_base;

        CP_WAIT0();
        __syncthreads();                 // A_t visible; prev-tile smem reuse done
        int tn = tile + GRID_P;
        if (tn < NTILE) {                // prefetch next tile into alternate buf
            const unsigned sAn_base = pb ? sA0_base : sA1_base;
            int m0 = tn * TROWS;
            for (int idx = tid; idx < TROWS * NCP; idx += 256) {
                int row = idx / NCP, q = idx % NCP;
                cp_async16(sAn_base + (row * SROW + q * 8) * 2,
                           hin + (size_t)(m0 + row) * (NCP * 8) + q * 8);
            }
        }
        CP_COMMIT();
        if (POOL && tid < TROWS) sbat[tid] = __ldg(batch + n0 + tid);

        // ---- GEMM1 + bias1 + ReLU -> sMid ----
#pragma unroll 1
        for (int mt = 0; mt < TROWS / 16; mt++) {
            float d0[4] = {0, 0, 0, 0}, d1[4] = {0, 0, 0, 0};
            int r0 = mt * 16;
#pragma unroll
            for (int kk = 0; kk < NKS1; kk++) {
                unsigned a[4];
                ldmA(a, sAc_base + ((r0 + lm_r) * SROW + kk * 16 + lm_c) * 2);
                mma16(d0, a, wf1[0][kk][0], wf1[0][kk][1]);
                mma16(d1, a, wf1[1][kk][0], wf1[1][kk][1]);
            }
#pragma unroll
            for (int nt = 0; nt < 2; nt++) {
                float* d = nt ? d1 : d0;
                int c0 = wbase + nt * 8 + 2 * qc;
                *(unsigned*)(sMid + (r0 + qr) * SROW + c0) =
                    packh2(fmaxf(d[0] + s_b1[c0], 0.f), fmaxf(d[1] + s_b1[c0 + 1], 0.f));
                *(unsigned*)(sMid + (r0 + 8 + qr) * SROW + c0) =
                    packh2(fmaxf(d[2] + s_b1[c0], 0.f), fmaxf(d[3] + s_b1[c0 + 1], 0.f));
            }
        }
        __syncthreads();

        // ---- GEMM2 + bias2: partial LN sums -> sp, fp16 values -> sAc ----
#pragma unroll 1
        for (int mt = 0; mt < TROWS / 16; mt++) {
            float d0[4] = {0, 0, 0, 0}, d1[4] = {0, 0, 0, 0};
            int r0 = mt * 16;
#pragma unroll
            for (int kk = 0; kk < 8; kk++) {
                unsigned a[4];
                ldmA(a, sMid_base + ((r0 + lm_r) * SROW + kk * 16 + lm_c) * 2);
                mma16(d0, a, wf2[0][kk][0], wf2[0][kk][1]);
                mma16(d1, a, wf2[1][kk][0], wf2[1][kk][1]);
            }
            {
                int c0 = wbase + 2 * qc, c1 = wbase + 8 + 2 * qc;
                d0[0] += s_b2[c0]; d0[1] += s_b2[c0 + 1];
                d0[2] += s_b2[c0]; d0[3] += s_b2[c0 + 1];
                d1[0] += s_b2[c1]; d1[1] += s_b2[c1 + 1];
                d1[2] += s_b2[c1]; d1[3] += s_b2[c1 + 1];
            }
            float sa = d0[0] + d0[1] + d1[0] + d1[1];
            float sb = d0[2] + d0[3] + d1[2] + d1[3];
            float qa = d0[0] * d0[0] + d0[1] * d0[1] + d1[0] * d1[0] + d1[1] * d1[1];
            float qb = d0[2] * d0[2] + d0[3] * d0[3] + d1[2] * d1[2] + d1[3] * d1[3];
#pragma unroll
            for (int o = 1; o <= 2; o <<= 1) {
                sa += __shfl_xor_sync(0xffffffffu, sa, o);
                sb += __shfl_xor_sync(0xffffffffu, sb, o);
                qa += __shfl_xor_sync(0xffffffffu, qa, o);
                qb += __shfl_xor_sync(0xffffffffu, qb, o);
            }
            if (qc == 0) {
                sp_s[(r0 + qr) * SPST + w] = sa;
                sp_s[(r0 + 8 + qr) * SPST + w] = sb;
                sp_q[(r0 + qr) * SPST + w] = qa;
                sp_q[(r0 + 8 + qr) * SPST + w] = qb;
            }
            {
                int c0 = wbase + 2 * qc;
                *(unsigned*)(sAc + (r0 + qr) * SROW + c0)      = packh2(d0[0], d0[1]);
                *(unsigned*)(sAc + (r0 + qr) * SROW + c0 + 8)  = packh2(d1[0], d1[1]);
                *(unsigned*)(sAc + (r0 + 8 + qr) * SROW + c0)     = packh2(d0[2], d0[3]);
                *(unsigned*)(sAc + (r0 + 8 + qr) * SROW + c0 + 8) = packh2(d1[2], d1[3]);
            }
        }
        __syncthreads();

        // ---- LN apply + ReLU + store (gmem for layers 0/1; smem stash for pool) ----
        for (int idx = tid; idx < TROWS * 16; idx += 256) {
            int row = idx >> 4, q = idx & 15;
            float4 sa = *(const float4*)(sp_s + row * SPST);
            float4 sb = *(const float4*)(sp_s + row * SPST + 4);
            float4 qa = *(const float4*)(sp_q + row * SPST);
            float4 qb = *(const float4*)(sp_q + row * SPST + 4);
            float s  = sa.x + sa.y + sa.z + sa.w + sb.x + sb.y + sb.z + sb.w;
            float s2 = qa.x + qa.y + qa.z + qa.w + qb.x + qb.y + qb.z + qb.w;
            float mean = s * (1.f / HD);
            float var = s2 * (1.f / HD) - mean * mean;
            float rstd = rsqrtf(var + 1e-5f);
            uint4 v = *(const uint4*)(sAc + row * SROW + q * 8);
            float2 v0 = __half22float2(*(half2*)&v.x);
            float2 v1 = __half22float2(*(half2*)&v.y);
            float2 v2 = __half22float2(*(half2*)&v.z);
            float2 v3 = __half22float2(*(half2*)&v.w);
            int c = q * 8;
            uint4 o;
            o.x = packh2(fmaxf((v0.x - mean) * rstd * s_g[c + 0] + s_bt[c + 0], 0.f),
                         fmaxf((v0.y - mean) * rstd * s_g[c + 1] + s_bt[c + 1], 0.f));
            o.y = packh2(fmaxf((v1.x - mean) * rstd * s_g[c + 2] + s_bt[c + 2], 0.f),
                         fmaxf((v1.y - mean) * rstd * s_g[c + 3] + s_bt[c + 3], 0.f));
            o.z = packh2(fmaxf((v2.x - mean) * rstd * s_g[c + 4] + s_bt[c + 4], 0.f),
                         fmaxf((v2.y - mean) * rstd * s_g[c + 5] + s_bt[c + 5], 0.f));
            o.w = packh2(fmaxf((v3.x - mean) * rstd * s_g[c + 6] + s_bt[c + 6], 0.f),
                         fmaxf((v3.y - mean) * rstd * s_g[c + 7] + s_bt[c + 7], 0.f));
            if (POOL) {
                *(uint4*)(sMid + row * SROW + c) = o;    // pooling consumes smem only
            } else {
                size_t off = (size_t)(n0 + row) * HD + c;
                *(uint4*)(out + off) = o;
                if (DUAL) *(uint4*)(hdup + off) = o;
            }
        }

        // ---- fused pooling: segmented reduction, 2 threads per column ----
        if (POOL) {
            __syncthreads();             // sMid stashes + sbat visible
            int j = tid & 127;
            int rbeg = (tid >> 7) * (TROWS / 2);       // 0 or 32
            int rend = rbeg + TROWS / 2;
            float acc = 0.f;
            int cnt = 0, cur = sbat[rbeg];
            for (int r = rbeg; r < rend; r++) {
                int gp = sbat[r];
                if (gp != cur) {
                    atomicAdd(&g_pool[cur * HD + j], acc);
                    if (j == 0) atomicAdd(&g_cnt[cur], cnt);
                    acc = 0.f; cnt = 0; cur = gp;
                }
                acc += __half2float(sMid[r * SROW + j]);
                cnt++;
            }
            atomicAdd(&g_pool[cur * HD + j], acc);
            if (j == 0) atomicAdd(&g_cnt[cur], cnt);
        }
        pb ^= 1;
    }
}

// ---------------- pooling epilogue ----------------
__global__ void finalize(float* __restrict__ out) {
    int g = blockIdx.x, j = threadIdx.x;
    float s = g_pool[g * HD + j];
    int c = g_cnt[g];
    float cf = (float)(c > 1 ? c : 1);
    out[g * 2 * HD + j]      = s / cf;
    out[g * 2 * HD + HD + j] = s;
}

// ---------------------------------------------------------------------------
extern "C" void kernel_launch(void* const* d_in, const int* in_sizes, int n_in,
                              void* d_out, int out_size) {
    const float* x     = (const float*)d_in[0];
    const int*   ei    = (const int*)d_in[1];
    const float* ea    = (const float*)d_in[2];
    const int*   batch = (const int*)d_in[3];
    const float* P[24];
    for (int i = 0; i < 24; i++) P[i] = (const float*)d_in[4 + i];
    const int* esrc = ei;
    const int* edst = ei + NE;

    __half *h5h, *h, *bufA, *bufB;
    cudaGetSymbolAddress((void**)&h5h, g_h5h);
    cudaGetSymbolAddress((void**)&h, g_h);
    cudaGetSymbolAddress((void**)&bufA, g_bufA);
    cudaGetSymbolAddress((void**)&bufB, g_bufB);

    cudaFuncSetAttribute(mlp_tc<IND, true, false>, cudaFuncAttributeMaxDynamicSharedMemorySize, SMEM_TOT);
    cudaFuncSetAttribute(mlp_tc<HD, true, false>,  cudaFuncAttributeMaxDynamicSharedMemorySize, SMEM_TOT);
    cudaFuncSetAttribute(mlp_tc<HD, false, true>,  cudaFuncAttributeMaxDynamicSharedMemorySize, SMEM_TOT);

    const int TB = 256;
    const int GEDGE = 3125;   // 3125*256/16 = 50000 edge slots, 8 iters

    // ---- layer 0 (din = 5, padded fp16; pool zeroing fused) ----
    copy5h<<<(NN + TB - 1) / TB, TB>>>(x);
    edge5h<<<(NE + TB - 1) / TB, TB>>>(esrc, edst, ea, P[0], P[1], x);
    mlp_tc<IND, true, false><<<GRID_P, 256, SMEM_TOT>>>(h5h, P[2], P[3], P[4], P[5], P[6], P[7], bufA, h, nullptr);

    // ---- layer 1 ----
    edge128h<<<GEDGE, TB>>>(esrc, edst, ea, P[8], P[9], bufA, h);
    mlp_tc<HD, true, false><<<GRID_P, 256, SMEM_TOT>>>(h, P[10], P[11], P[12], P[13], P[14], P[15], bufB, h, nullptr);

    // ---- layer 2 (pooling fused; no gmem output store) ----
    edge128h<<<GEDGE, TB>>>(esrc, edst, ea, P[16], P[17], bufB, h);
    mlp_tc<HD, false, true><<<GRID_P, 256, SMEM_TOT>>>(h, P[18], P[19], P[20], P[21], P[22], P[23], nullptr, nullptr, batch);

    // ---- finalize ----
    finalize<<<NG, HD>>>((float*)d_out);
}